// round 2
// baseline (speedup 1.0000x reference)
#include <cuda_runtime.h>

// Problem constants (fixed by setup_inputs)
#define BB 16
#define HH 2048
#define WW 2048
#define SS 5000
#define TOTAL (BB * SS)          // 80000 stations
#define THREADS 256
#define NBLK ((TOTAL + THREADS - 1) / THREADS)   // 313

__device__ float        g_partials[NBLK];
__device__ unsigned int g_count;   // zero-initialized at module load; reset by last block

__global__ void __launch_bounds__(THREADS)
station_loss_fused_kernel(const float* __restrict__ pred,
                          const int*   __restrict__ pos,
                          const float* __restrict__ runoff,
                          float*       __restrict__ out)
{
    int idx = blockIdx.x * THREADS + threadIdx.x;
    float err2 = 0.0f;

    if (idx < TOTAL) {
        int b  = idx / SS;
        // station_positions[b, s, 0] = px (width/x), [b, s, 1] = py (height/y)
        int2 p = __ldg(reinterpret_cast<const int2*>(pos) + idx);
        int px = p.x;
        int py = p.y;

        const float* base = pred + (size_t)b * (size_t)(HH * WW);

        float sum = 0.0f;
        float cnt = 0.0f;
        #pragma unroll
        for (int dy = -1; dy <= 1; ++dy) {
            int y   = py + dy;
            bool vy = (y >= 0) & (y < HH);
            int yc  = min(max(y, 0), HH - 1);
            const float* row = base + (size_t)yc * WW;
            #pragma unroll
            for (int dx = -1; dx <= 1; ++dx) {
                int x   = px + dx;
                bool v  = vy & (x >= 0) & (x < WW);
                int xc  = min(max(x, 0), WW - 1);
                float val = __ldg(row + xc);
                sum += v ? val  : 0.0f;
                cnt += v ? 1.0f : 0.0f;
            }
        }
        float avg = sum / cnt;
        float d   = avg - __ldg(runoff + idx);
        err2 = d * d;
    }

    // Deterministic block reduction: warp shuffle then shared tree.
    __shared__ float warp_sums[THREADS / 32];
    #pragma unroll
    for (int off = 16; off > 0; off >>= 1)
        err2 += __shfl_down_sync(0xFFFFFFFFu, err2, off);

    int lane = threadIdx.x & 31;
    int wid  = threadIdx.x >> 5;
    if (lane == 0) warp_sums[wid] = err2;
    __syncthreads();

    __shared__ bool is_last;
    if (threadIdx.x == 0) {
        float v = 0.0f;
        #pragma unroll
        for (int i = 0; i < THREADS / 32; ++i)
            v += warp_sums[i];
        g_partials[blockIdx.x] = v;
        __threadfence();
        unsigned int done = atomicAdd(&g_count, 1u);
        is_last = (done == NBLK - 1);
    }
    __syncthreads();

    // Last block to finish performs the deterministic final reduction.
    if (is_last) {
        __shared__ float sh[THREADS];
        float v = 0.0f;
        for (int i = threadIdx.x; i < NBLK; i += THREADS)
            v += g_partials[i];
        sh[threadIdx.x] = v;
        __syncthreads();
        #pragma unroll
        for (int off = THREADS / 2; off > 0; off >>= 1) {
            if (threadIdx.x < off) sh[threadIdx.x] += sh[threadIdx.x + off];
            __syncthreads();
        }
        if (threadIdx.x == 0) {
            out[0]  = sh[0] / (float)TOTAL;
            g_count = 0;   // re-arm for next graph replay
        }
    }
}

extern "C" void kernel_launch(void* const* d_in, const int* in_sizes, int n_in,
                              void* d_out, int out_size)
{
    const float* pred   = (const float*)d_in[0];  // (B,1,H,W) f32
    const int*   pos    = (const int*)  d_in[1];  // (B,S,2)  i32
    const float* runoff = (const float*)d_in[2];  // (B,S)    f32
    float* out = (float*)d_out;

    station_loss_fused_kernel<<<NBLK, THREADS>>>(pred, pos, runoff, out);
}

// round 3
// speedup vs baseline: 1.4963x; 1.4963x over previous
#include <cuda_runtime.h>

#define BB 16
#define HH 2048
#define WW 2048
#define SS 5000
#define TOTAL (BB * SS)          // 80000 stations
#define THREADS 256
#define NBLK ((TOTAL + THREADS - 1) / THREADS)   // 313

__device__ float        g_partials[NBLK];
__device__ unsigned int g_count;   // zero at module load; re-armed by last block

__device__ __forceinline__ unsigned atomic_inc_acqrel(unsigned int* p) {
    unsigned old;
    asm volatile("atom.acq_rel.gpu.global.add.u32 %0, [%1], %2;"
                 : "=r"(old) : "l"(p), "r"(1u) : "memory");
    return old;
}

__global__ void __launch_bounds__(THREADS)
station_loss_fused_kernel(const float* __restrict__ pred,
                          const int*   __restrict__ pos,
                          const float* __restrict__ runoff,
                          float*       __restrict__ out)
{
    int idx = blockIdx.x * THREADS + threadIdx.x;
    float err2 = 0.0f;

    if (idx < TOTAL) {
        int b  = idx / SS;
        int2 p = __ldg(reinterpret_cast<const int2*>(pos) + idx);
        int px = p.x;   // width index
        int py = p.y;   // height index

        const float* base = pred + (size_t)b * (size_t)(HH * WW);
        float avg;

        if (px >= 1 && px <= WW - 2 && py >= 1 && py <= HH - 2) {
            // Fast path: all 9 taps valid. Cover [px-1, px+1] with two
            // aligned float2 loads per row -> 6 LDG.64 total, issued up front.
            int a   = (px - 1) >> 1;                 // float2 index
            int off = (px - 1) & 1;                  // 0 or 1 within v0
            const float2* r0 = reinterpret_cast<const float2*>(base + (size_t)(py - 1) * WW);
            const float2* r1 = reinterpret_cast<const float2*>(base + (size_t)(py    ) * WW);
            const float2* r2 = reinterpret_cast<const float2*>(base + (size_t)(py + 1) * WW);

            float2 a0 = __ldg(r0 + a), b0 = __ldg(r0 + a + 1);
            float2 a1 = __ldg(r1 + a), b1 = __ldg(r1 + a + 1);
            float2 a2 = __ldg(r2 + a), b2 = __ldg(r2 + a + 1);

            float s0 = off ? (a0.y + b0.x + b0.y) : (a0.x + a0.y + b0.x);
            float s1 = off ? (a1.y + b1.x + b1.y) : (a1.x + a1.y + b1.x);
            float s2 = off ? (a2.y + b2.x + b2.y) : (a2.x + a2.y + b2.x);
            avg = (s0 + s1 + s2) * (1.0f / 9.0f);
        } else {
            // Edge path (rare): masked 9-tap with clamped coords.
            float sum = 0.0f, cnt = 0.0f;
            #pragma unroll
            for (int dy = -1; dy <= 1; ++dy) {
                int y   = py + dy;
                bool vy = (y >= 0) & (y < HH);
                int yc  = min(max(y, 0), HH - 1);
                const float* row = base + (size_t)yc * WW;
                #pragma unroll
                for (int dx = -1; dx <= 1; ++dx) {
                    int x  = px + dx;
                    bool v = vy & (x >= 0) & (x < WW);
                    int xc = min(max(x, 0), WW - 1);
                    float val = __ldg(row + xc);
                    sum += v ? val  : 0.0f;
                    cnt += v ? 1.0f : 0.0f;
                }
            }
            avg = sum / cnt;
        }

        float d = avg - __ldg(runoff + idx);
        err2 = d * d;
    }

    // Deterministic block reduction.
    __shared__ float warp_sums[THREADS / 32];
    #pragma unroll
    for (int off = 16; off > 0; off >>= 1)
        err2 += __shfl_down_sync(0xFFFFFFFFu, err2, off);

    int lane = threadIdx.x & 31;
    int wid  = threadIdx.x >> 5;
    if (lane == 0) warp_sums[wid] = err2;
    __syncthreads();

    __shared__ bool is_last;
    if (threadIdx.x == 0) {
        float v = 0.0f;
        #pragma unroll
        for (int i = 0; i < THREADS / 32; ++i)
            v += warp_sums[i];
        g_partials[blockIdx.x] = v;
        // acq_rel atomic: releases the partial store, no L1-flushing membar.
        unsigned done = atomic_inc_acqrel(&g_count);
        is_last = (done == NBLK - 1);
    }
    __syncthreads();

    if (is_last) {
        __shared__ float sh[THREADS];
        float v = 0.0f;
        for (int i = threadIdx.x; i < NBLK; i += THREADS)
            v += __ldcg(&g_partials[i]);   // L2 read, bypass L1
        sh[threadIdx.x] = v;
        __syncthreads();
        #pragma unroll
        for (int off = THREADS / 2; off > 0; off >>= 1) {
            if (threadIdx.x < off) sh[threadIdx.x] += sh[threadIdx.x + off];
            __syncthreads();
        }
        if (threadIdx.x == 0) {
            out[0]  = sh[0] / (float)TOTAL;
            g_count = 0;   // re-arm for next graph replay
        }
    }
}

extern "C" void kernel_launch(void* const* d_in, const int* in_sizes, int n_in,
                              void* d_out, int out_size)
{
    const float* pred   = (const float*)d_in[0];  // (B,1,H,W) f32
    const int*   pos    = (const int*)  d_in[1];  // (B,S,2)  i32
    const float* runoff = (const float*)d_in[2];  // (B,S)    f32
    float* out = (float*)d_out;

    station_loss_fused_kernel<<<NBLK, THREADS>>>(pred, pos, runoff, out);
}